// round 3
// baseline (speedup 1.0000x reference)
#include <cuda_runtime.h>

// ---------------- device scratch (no allocations allowed) ----------------
__device__ float g_x1[256 * 12 * 64 * 64];   // after layer 0 (tanh'd)
__device__ float g_x2[256 * 48 * 32 * 32];   // after layer 1 (tanh'd)
__device__ float g_tld[256];                 // per-batch tanh logdet accumulators
__device__ float g_scalar;                   // sum of per-layer scalar logdets

#define X_ELEMS (256 * 192 * 16 * 16)

// ---------------- packed f32x2 helpers ----------------
__device__ __forceinline__ void ffma2(unsigned long long& d, unsigned long long a,
                                      unsigned long long b) {
    asm("fma.rn.f32x2 %0, %1, %2, %0;" : "+l"(d) : "l"(a), "l"(b));
}
__device__ __forceinline__ float2 up2(unsigned long long v) {
    float2 f;
    asm("mov.b64 {%0,%1}, %2;" : "=f"(f.x), "=f"(f.y) : "l"(v));
    return f;
}
__device__ __forceinline__ float wred(float v) {
    #pragma unroll
    for (int o = 16; o; o >>= 1) v += __shfl_xor_sync(0xffffffffu, v, o);
    return v;
}

// ---------------- init / finalize ----------------
__global__ void init_kernel() {
    int t = threadIdx.x;
    g_tld[t] = 0.f;
    if (t == 0) g_scalar = 0.f;
}
__global__ void fin_kernel(float* __restrict__ out) {
    int t = threadIdx.x;
    out[X_ELEMS + t] = g_scalar + g_tld[t];
}

// ---------------- scalar logdet: conv spectral logdet (2nd-order trace series)
//                  + actnorm n^2 * sum(als) ----------------
__device__ __forceinline__ float2 cmul(float2 a, float2 b) {
    return make_float2(a.x * b.x - a.y * b.y, a.x * b.y + a.y * b.x);
}

__global__ void logdet_kernel(const float* __restrict__ K0, const float* __restrict__ a0,
                              const float* __restrict__ K1, const float* __restrict__ a1,
                              const float* __restrict__ K2, const float* __restrict__ a2) {
    const int L = blockIdx.x;
    const float* K = (L == 0) ? K0 : ((L == 1) ? K1 : K2);
    const float* als = (L == 0) ? a0 : ((L == 1) ? a1 : a2);
    const int c = (L == 0) ? 12 : ((L == 1) ? 48 : 192);
    const int n = (L == 0) ? 64 : ((L == 1) ? 32 : 16);

    __shared__ float sh_t[9];
    __shared__ float shS[81];
    __shared__ float red[16];
    const int tid = threadIdx.x;
    if (tid < 9) sh_t[tid] = 0.f;
    if (tid < 81) shS[tid] = 0.f;
    __syncthreads();

    // t_a = tr(K_a);  S_ab = tr(K_a K_b) = sum_ij K_a[i,j] K_b[j,i]
    float a81[81];
    float t9[9];
    #pragma unroll
    for (int k = 0; k < 81; k++) a81[k] = 0.f;
    #pragma unroll
    for (int k = 0; k < 9; k++) t9[k] = 0.f;

    for (int idx = tid; idx < c * c; idx += 256) {
        int i = idx / c, j = idx - i * c;
        const float* Ka = K + (size_t)(i * c + j) * 9;
        const float* Kb = K + (size_t)(j * c + i) * 9;
        float av[9], bv[9];
        #pragma unroll
        for (int a = 0; a < 9; a++) { av[a] = Ka[a]; bv[a] = Kb[a]; }
        #pragma unroll
        for (int a = 0; a < 9; a++)
            #pragma unroll
            for (int b = 0; b < 9; b++) a81[a * 9 + b] += av[a] * bv[b];
        if (i == j) {
            #pragma unroll
            for (int a = 0; a < 9; a++) t9[a] += av[a];
        }
    }
    #pragma unroll
    for (int k = 0; k < 81; k++) atomicAdd(&shS[k], a81[k]);
    #pragma unroll
    for (int k = 0; k < 9; k++) atomicAdd(&sh_t[k], t9[k]);
    __syncthreads();

    // frequency sum:  log|det Khat(u,v)| ~= Re tr(M) - Re tr(M^2)/2,
    // M = e^{i theta} Khat - I, theta = 2 pi (u+v)/n.
    // With T = sum_a t_a phi_a, T2 = sum_ab S_ab phi_a phi_b:
    //   Re tr(M)   = A - c,         A = Re(e^{i th} T)
    //   Re tr(M^2) = B - 2A + c,    B = Re(e^{2i th} T2)
    //   contrib    = 2A - 1.5c - 0.5B
    float part = 0.f;
    for (int f = tid; f < n * n; f += 256) {
        int u = f / n, v = f - u * n;
        float su, cu, sv, cv;
        sincosf(-6.283185307179586f * (float)u / (float)n, &su, &cu);
        sincosf(-6.283185307179586f * (float)v / (float)n, &sv, &cv);
        float2 eu = make_float2(cu, su), ev = make_float2(cv, sv);
        float2 pU[3] = {make_float2(1.f, 0.f), eu, cmul(eu, eu)};
        float2 pV[3] = {make_float2(1.f, 0.f), ev, cmul(ev, ev)};
        float2 ph[9];
        #pragma unroll
        for (int dy = 0; dy < 3; dy++)
            #pragma unroll
            for (int dx = 0; dx < 3; dx++) ph[dy * 3 + dx] = cmul(pU[dy], pV[dx]);

        float2 T = make_float2(0.f, 0.f), T2 = make_float2(0.f, 0.f);
        #pragma unroll
        for (int a = 0; a < 9; a++) {
            T.x += sh_t[a] * ph[a].x;
            T.y += sh_t[a] * ph[a].y;
        }
        #pragma unroll
        for (int a = 0; a < 9; a++) {
            float2 inner = make_float2(0.f, 0.f);
            #pragma unroll
            for (int b = 0; b < 9; b++) {
                float s = shS[a * 9 + b];
                inner.x += s * ph[b].x;
                inner.y += s * ph[b].y;
            }
            float2 pi = cmul(ph[a], inner);
            T2.x += pi.x;
            T2.y += pi.y;
        }
        float2 e1 = cmul(pU[1], pV[1]);
        e1.y = -e1.y;                 // e^{+i theta}
        float2 e2 = cmul(e1, e1);     // e^{+2i theta}
        float A = e1.x * T.x - e1.y * T.y;
        float B = e2.x * T2.x - e2.y * T2.y;
        part += 2.f * A - 1.5f * (float)c - 0.5f * B;
    }

    float as = 0.f;
    for (int k = tid; k < c; k += 256) as += als[k];

    float w1 = wred(part);
    float w2 = wred(as);
    int wid = tid >> 5;
    if ((tid & 31) == 0) { red[wid] = w1; red[wid + 8] = w2; }
    __syncthreads();
    if (tid == 0) {
        float s1 = 0.f, s2 = 0.f;
        #pragma unroll
        for (int w = 0; w < 8; w++) { s1 += red[w]; s2 += red[w + 8]; }
        atomicAdd(&g_scalar, s1 + (float)(n * n) * s2);
    }
}

// ---------------- fused layer kernel: squeeze + circular conv + bias +
//                  actnorm + (tanh + per-batch logdet) ----------------
// X: pre-squeeze input [B, CPREV, 2N, 2N]; Y: output [B, 4*CPREV, N, N]
// Block: 256 threads = 16x16 spatial tile; 4 batches/thread packed as f32x2 pairs;
// OUT_BLK output channels per block; input channels staged CI_CHUNK at a time.
template <int CPREV, int N, int CI_CHUNK, int OUT_BLK, bool DO_TANH>
__global__ void __launch_bounds__(256, 1)
conv_layer(const float* __restrict__ X, const float* __restrict__ Kw,
           const float* __restrict__ cb, const float* __restrict__ ab,
           const float* __restrict__ als, float* __restrict__ Y) {
    constexpr int CIN = 4 * CPREV;
    constexpr int COUT = CIN;
    constexpr int H = 2 * N;
    constexpr int S_FLOATS = CI_CHUNK * 324 * 4;  // [ci][18][18][nb=4]
    extern __shared__ float smem[];
    float* S = smem;
    float2* KS = (float2*)(smem + S_FLOATS);      // [ci][tap][o] duplicated-pack

    const int tid = threadIdx.x;
    const int b0 = blockIdx.x * 4;
    constexpr int TILES_X = N / 16;
    const int ty = (blockIdx.y / TILES_X) * 16;
    const int tx = (blockIdx.y % TILES_X) * 16;
    const int og = blockIdx.z * OUT_BLK;
    const int py = tid >> 4, px = tid & 15;

    unsigned long long accA[OUT_BLK], accB[OUT_BLK];
    #pragma unroll
    for (int o = 0; o < OUT_BLK; o++) { accA[o] = 0ull; accB[o] = 0ull; }

    for (int ci0 = 0; ci0 < CIN; ci0 += CI_CHUNK) {
        __syncthreads();
        // stage squeezed input tile (with circular halo) for 4 batches
        for (int idx = tid; idx < CI_CHUNK * 324; idx += 256) {
            int ci = idx / 324;
            int rem = idx - ci * 324;
            int yy = rem / 18, xx = rem - yy * 18;
            int cig = ci0 + ci;
            int g = cig / CPREV;
            int cc = cig - g * CPREV;
            int gy = ty + yy - 1;
            if (gy < 0) gy += N;
            if (gy >= N) gy -= N;
            int gx = tx + xx - 1;
            if (gx < 0) gx += N;
            if (gx >= N) gx -= N;
            // squeeze groups: (hs,ws) = (0,0),(1,1),(0,1),(1,0)
            int sy = 2 * gy + (g & 1);
            int sx = 2 * gx + ((g ^ (g >> 1)) & 1);
            size_t base = ((size_t)cc * H + sy) * H + sx;
            size_t bstr = (size_t)CPREV * H * H;
            float4 val;
            val.x = X[base + (size_t)(b0 + 0) * bstr];
            val.y = X[base + (size_t)(b0 + 1) * bstr];
            val.z = X[base + (size_t)(b0 + 2) * bstr];
            val.w = X[base + (size_t)(b0 + 3) * bstr];
            *(float4*)(S + idx * 4) = val;
        }
        // stage kernel weights, duplicated for f32x2
        for (int idx = tid; idx < CI_CHUNK * 9 * OUT_BLK; idx += 256) {
            int ci = idx / (9 * OUT_BLK);
            int rem = idx - ci * 9 * OUT_BLK;
            int tap = rem / OUT_BLK;
            int o = rem - tap * OUT_BLK;
            float k = Kw[((size_t)(og + o) * CIN + (ci0 + ci)) * 9 + tap];
            KS[idx] = make_float2(k, k);
        }
        __syncthreads();

        #pragma unroll 1
        for (int ci = 0; ci < CI_CHUNK; ci++) {
            const float* Sci = S + ci * 1296;
            ulonglong2 v[9];
            #pragma unroll
            for (int dy = 0; dy < 3; dy++)
                #pragma unroll
                for (int dx = 0; dx < 3; dx++)
                    v[dy * 3 + dx] =
                        *(const ulonglong2*)(Sci + ((py + dy) * 18 + (px + dx)) * 4);
            const float2* Kci = KS + ci * 9 * OUT_BLK;
            #pragma unroll
            for (int o = 0; o < OUT_BLK; o += 2) {
                #pragma unroll
                for (int tap = 0; tap < 9; tap++) {
                    ulonglong2 kk = *(const ulonglong2*)(Kci + tap * OUT_BLK + o);
                    ffma2(accA[o], kk.x, v[tap].x);
                    ffma2(accB[o], kk.x, v[tap].y);
                    ffma2(accA[o + 1], kk.y, v[tap].x);
                    ffma2(accB[o + 1], kk.y, v[tap].y);
                }
            }
        }
    }

    // epilogue: bias + actnorm (+ tanh + logdet)
    const int i = ty + py, j = tx + px;
    float ld[4] = {0.f, 0.f, 0.f, 0.f};
    #pragma unroll 1
    for (int o = 0; o < OUT_BLK; o++) {
        float e = expf(als[og + o]);
        float abv = ab[og + o];
        float cbv = cb[((size_t)(og + o) * N + i) * N + j];
        float2 p01 = up2(accA[o]);
        float2 p23 = up2(accB[o]);
        float zs[4] = {p01.x, p01.y, p23.x, p23.y};
        #pragma unroll
        for (int nb = 0; nb < 4; nb++) {
            float z = (zs[nb] + cbv) * e + abv;
            float outv;
            if (DO_TANH) {
                float t = tanhf(z);
                outv = t;
                ld[nb] += log1pf(-t * t);
            } else {
                outv = z;
            }
            Y[(((size_t)(b0 + nb) * COUT + (og + o)) * N + i) * N + j] = outv;
        }
    }

    if (DO_TANH) {
        #pragma unroll
        for (int nb = 0; nb < 4; nb++) ld[nb] = wred(ld[nb]);
        __syncthreads();
        float* red = S;  // reuse smem
        if ((tid & 31) == 0) {
            int w = tid >> 5;
            red[w * 4 + 0] = ld[0];
            red[w * 4 + 1] = ld[1];
            red[w * 4 + 2] = ld[2];
            red[w * 4 + 3] = ld[3];
        }
        __syncthreads();
        if (tid < 4) {
            float s = 0.f;
            #pragma unroll
            for (int w = 0; w < 8; w++) s += red[w * 4 + tid];
            atomicAdd(&g_tld[b0 + tid], s);
        }
    }
}

// ---------------- launch ----------------
extern "C" void kernel_launch(void* const* d_in, const int* in_sizes, int n_in,
                              void* d_out, int out_size) {
    const float* x = (const float*)d_in[0];
    const float* k0 = (const float*)d_in[1];
    const float* cb0 = (const float*)d_in[2];
    const float* ab0 = (const float*)d_in[3];
    const float* als0 = (const float*)d_in[4];
    const float* k1 = (const float*)d_in[5];
    const float* cb1 = (const float*)d_in[6];
    const float* ab1 = (const float*)d_in[7];
    const float* als1 = (const float*)d_in[8];
    const float* k2 = (const float*)d_in[9];
    const float* cb2 = (const float*)d_in[10];
    const float* ab2 = (const float*)d_in[11];
    const float* als2 = (const float*)d_in[12];
    float* out = (float*)d_out;

    float *x1, *x2;
    cudaGetSymbolAddress((void**)&x1, g_x1);
    cudaGetSymbolAddress((void**)&x2, g_x2);

    const int SM0 = 12 * 324 * 4 * 4 + 12 * 9 * 12 * 8;   // 72,576 B
    const int SM12 = 24 * 324 * 4 * 4 + 24 * 9 * 16 * 8;  // 152,064 B
    cudaFuncSetAttribute((const void*)conv_layer<3, 64, 12, 12, true>,
                         cudaFuncAttributeMaxDynamicSharedMemorySize, SM0);
    cudaFuncSetAttribute((const void*)conv_layer<12, 32, 24, 16, true>,
                         cudaFuncAttributeMaxDynamicSharedMemorySize, SM12);
    cudaFuncSetAttribute((const void*)conv_layer<48, 16, 24, 16, false>,
                         cudaFuncAttributeMaxDynamicSharedMemorySize, SM12);

    init_kernel<<<1, 256>>>();
    logdet_kernel<<<3, 256>>>(k0, als0, k1, als1, k2, als2);

    // layer 0: [256,3,128,128] -> [256,12,64,64], tanh
    conv_layer<3, 64, 12, 12, true><<<dim3(64, 16, 1), 256, SM0>>>(x, k0, cb0, ab0, als0, x1);
    // layer 1: [256,12,64,64] -> [256,48,32,32], tanh
    conv_layer<12, 32, 24, 16, true><<<dim3(64, 4, 3), 256, SM12>>>(x1, k1, cb1, ab1, als1, x2);
    // layer 2: [256,48,32,32] -> [256,192,16,16] straight into d_out
    conv_layer<48, 16, 24, 16, false><<<dim3(64, 1, 12), 256, SM12>>>(x2, k2, cb2, ab2, als2, out);

    fin_kernel<<<1, 256>>>(out);
}